// round 3
// baseline (speedup 1.0000x reference)
#include <cuda_runtime.h>
#include <cstdint>

typedef unsigned long long u64;

#define NB 6
#define BUCKET 10
#define PERM_MAX 262656          // n=262144 + 6*32 pad, rounded up to 512
#define MAIN_THREADS 512
#define MAIN_WARPS 16

// ---- packed weight image float offsets ----
#define OFF_T1B 0                // [c][ip][o] f32x2 pairs: 6*64*8*2 = 6144
#define OFF_T1P 6144             // 6144
#define OFF_WOB 12288            // [c][ip] pairs: 6*64*2 = 768 (Wout[64+2ip+h])
#define OFF_WOP 13056            // 768 (Wout[192+2ip+h])
#define OFF_W2  13824            // [c][o][jj] pairs: 6*64*16*2 = 12288
#define OFF_WO2 26112            // [c][o]: 384 (Wout[o])
#define OFF_M1B 26496            // [c][o]: 48 (W1b[...][128])
#define OFF_M1P 26544            // 48
#define OFF_B1B 26592            // 48
#define OFF_B1P 26640            // 48
#define OFF_B2  26688            // 384
#define OFF_BOUT 27072           // 6
#define WPK_F   27080            // padded to float4

#define STAGE_F_PER_WARP 1024    // 32 rows x 8 float4
#define SMEM_FLOATS (WPK_F + MAIN_WARPS*STAGE_F_PER_WARP)   // 43464
#define SMEM_BYTES  (SMEM_FLOATS*4)                         // 173856

__device__ int   g_perm[PERM_MAX];
__device__ int   g_cnt[NB];
__device__ int   g_start[NB];
__device__ int   g_cur[NB];
__device__ float g_wpk[WPK_F];

// ---------------- f32x2 helpers ----------------
__device__ __forceinline__ u64 f2fma(u64 a, u64 b, u64 c) {
    u64 d;
    asm("fma.rn.f32x2 %0, %1, %2, %3;" : "=l"(d) : "l"(a), "l"(b), "l"(c));
    return d;
}
__device__ __forceinline__ float lo32(u64 a) { return __uint_as_float((unsigned)a); }
__device__ __forceinline__ float hi32(u64 a) { return __uint_as_float((unsigned)(a >> 32)); }
__device__ __forceinline__ u64 pk(float lo, float hi) {
    u64 r;
    asm("mov.b64 %0, {%1, %2};" : "=l"(r) : "f"(lo), "f"(hi));
    return r;
}

// ---------------- prep kernels ----------------
__global__ void k_init(int cap) {
    int i = blockIdx.x * blockDim.x + threadIdx.x;
    if (i < cap) g_perm[i] = -1;
    if (i < NB) { g_cnt[i] = 0; g_cur[i] = 0; }
}

__global__ void k_pack(const float* __restrict__ W1b, const float* __restrict__ b1b,
                       const float* __restrict__ W1pa, const float* __restrict__ b1pa,
                       const float* __restrict__ W2, const float* __restrict__ b2,
                       const float* __restrict__ Wout, const float* __restrict__ bout) {
    int i = blockIdx.x * blockDim.x + threadIdx.x;
    if (i >= WPK_F) return;
    float v = 0.0f;
    if (i < OFF_T1P) {                 // T1B
        int h = i & 1, t = i >> 1;
        int o = t & 7, ip = (t >> 3) & 63, c = t >> 9;
        v = W1b[(c * 8 + o) * 129 + 2 * ip + h];
    } else if (i < OFF_WOB) {          // T1P
        int j = i - OFF_T1P;
        int h = j & 1, t = j >> 1;
        int o = t & 7, ip = (t >> 3) & 63, c = t >> 9;
        v = W1pa[(c * 8 + o) * 129 + 2 * ip + h];
    } else if (i < OFF_WOP) {          // WOB
        int j = i - OFF_WOB;
        int h = j & 1, t = j >> 1;
        int ip = t & 63, c = t >> 6;
        v = Wout[c * 320 + 64 + 2 * ip + h];
    } else if (i < OFF_W2) {           // WOP
        int j = i - OFF_WOP;
        int h = j & 1, t = j >> 1;
        int ip = t & 63, c = t >> 6;
        v = Wout[c * 320 + 192 + 2 * ip + h];
    } else if (i < OFF_WO2) {          // W2
        int j = i - OFF_W2;
        int h = j & 1, t = j >> 1;
        int jj = t & 15, o = (t >> 4) & 63, c = t >> 10;
        v = W2[(c * 64 + o) * 32 + 2 * jj + h];
    } else if (i < OFF_M1B) {          // WO2
        int j = i - OFF_WO2;
        int o = j & 63, c = j >> 6;
        v = Wout[c * 320 + o];
    } else if (i < OFF_M1P) {          // M1B
        int j = i - OFF_M1B;
        int o = j & 7, c = j >> 3;
        v = W1b[(c * 8 + o) * 129 + 128];
    } else if (i < OFF_B1B) {          // M1P
        int j = i - OFF_M1P;
        int o = j & 7, c = j >> 3;
        v = W1pa[(c * 8 + o) * 129 + 128];
    } else if (i < OFF_B1P) {          // B1B
        int j = i - OFF_B1B;
        v = b1b[j];
    } else if (i < OFF_B2) {           // B1P
        int j = i - OFF_B1P;
        v = b1pa[j];
    } else if (i < OFF_BOUT) {         // B2
        int j = i - OFF_B2;
        v = b2[j];
    } else if (i < OFF_BOUT + NB) {    // BOUT
        v = bout[i - OFF_BOUT];
    }
    g_wpk[i] = v;
}

__global__ void k_count(const int* __restrict__ ply, int n) {
    __shared__ int h[NB];
    if (threadIdx.x < NB) h[threadIdx.x] = 0;
    __syncthreads();
    int i = blockIdx.x * blockDim.x + threadIdx.x;
    if (i < n) {
        int c = ply[i] / BUCKET;
        c = min(max(c, 0), NB - 1);
        atomicAdd(&h[c], 1);
    }
    __syncthreads();
    if (threadIdx.x < NB) atomicAdd(&g_cnt[threadIdx.x], h[threadIdx.x]);
}

__global__ void k_offsets() {
    int base = 0;
    for (int c = 0; c < NB; c++) {
        g_start[c] = base;
        base += ((g_cnt[c] + 31) >> 5) << 5;   // pad each bucket to warp multiple
        if (base > PERM_MAX) base = PERM_MAX;  // defensive clamp
    }
}

__global__ void k_scatter(const int* __restrict__ ply, int n) {
    int i = blockIdx.x * blockDim.x + threadIdx.x;
    bool act = i < n;
    int c = -1;
    if (act) {
        c = ply[i] / BUCKET;
        c = min(max(c, 0), NB - 1);
    }
    unsigned lane = threadIdx.x & 31;
    for (int cc = 0; cc < NB; cc++) {
        unsigned m = __ballot_sync(0xffffffffu, c == cc);
        if (c == cc) {
            int leader = __ffs(m) - 1;
            int cnt = __popc(m);
            int rank = __popc(m & ((1u << lane) - 1u));
            int pos = 0;
            if ((int)lane == leader) pos = atomicAdd(&g_cur[cc], cnt);
            pos = __shfl_sync(m, pos, leader);
            g_perm[g_start[cc] + pos + rank] = i | (cc << 24);
        }
    }
}

// ---------------- main kernel ----------------
// One thread = one sample; warps are bucket-uniform (sorted perm).
// x rows staged per-warp through XOR-swizzled smem so global loads are coalesced.
__device__ __forceinline__ void pass_stream(
    const float4* __restrict__ x4, const ulonglong2* __restrict__ T1,
    const u64* __restrict__ WO, float4* stg, const ulonglong2* stgu,
    int lane, int s, u64& accO, u64 acc[8]) {
    const int r = lane >> 3, ch = lane & 7;
#pragma unroll
    for (int T = 0; T < 4; T++) {
        __syncwarp();
#pragma unroll
        for (int k = 0; k < 8; k++) {
            int rr = k * 4 + r;
            int rowp = __shfl_sync(0xffffffffu, s, rr);
            stg[rr * 8 + (ch ^ (rr & 7))] = x4[(size_t)rowp * 32 + T * 8 + ch];
        }
        __syncwarp();
#pragma unroll
        for (int t = 0; t < 8; t++) {
            ulonglong2 xv = stgu[lane * 8 + (t ^ (lane & 7))];
            int ip0 = T * 16 + 2 * t;
            {
                ulonglong2 wA = T1[ip0 * 4 + 0], wB = T1[ip0 * 4 + 1];
                ulonglong2 wC = T1[ip0 * 4 + 2], wD = T1[ip0 * 4 + 3];
                acc[0] = f2fma(wA.x, xv.x, acc[0]);
                acc[1] = f2fma(wA.y, xv.x, acc[1]);
                acc[2] = f2fma(wB.x, xv.x, acc[2]);
                acc[3] = f2fma(wB.y, xv.x, acc[3]);
                acc[4] = f2fma(wC.x, xv.x, acc[4]);
                acc[5] = f2fma(wC.y, xv.x, acc[5]);
                acc[6] = f2fma(wD.x, xv.x, acc[6]);
                acc[7] = f2fma(wD.y, xv.x, acc[7]);
                accO = f2fma(WO[ip0], xv.x, accO);
            }
            {
                int ip1 = ip0 + 1;
                ulonglong2 wA = T1[ip1 * 4 + 0], wB = T1[ip1 * 4 + 1];
                ulonglong2 wC = T1[ip1 * 4 + 2], wD = T1[ip1 * 4 + 3];
                acc[0] = f2fma(wA.x, xv.y, acc[0]);
                acc[1] = f2fma(wA.y, xv.y, acc[1]);
                acc[2] = f2fma(wB.x, xv.y, acc[2]);
                acc[3] = f2fma(wB.y, xv.y, acc[3]);
                acc[4] = f2fma(wC.x, xv.y, acc[4]);
                acc[5] = f2fma(wC.y, xv.y, acc[5]);
                acc[6] = f2fma(wD.x, xv.y, acc[6]);
                acc[7] = f2fma(wD.y, xv.y, acc[7]);
                accO = f2fma(WO[ip1], xv.y, accO);
            }
        }
    }
}

__global__ __launch_bounds__(MAIN_THREADS, 1)
void k_main(const float4* __restrict__ xb4, const float4* __restrict__ xp4,
            const float* __restrict__ mobv, float* __restrict__ out) {
    extern __shared__ float sw[];
    {
        float4* d = (float4*)sw;
        const float4* sp = (const float4*)g_wpk;
        for (int i = threadIdx.x; i < WPK_F / 4; i += MAIN_THREADS) d[i] = sp[i];
    }
    __syncthreads();

    const int lane = threadIdx.x & 31;
    const int wid = threadIdx.x >> 5;
    float4* stg = (float4*)(sw + WPK_F) + wid * (STAGE_F_PER_WARP / 4);
    const ulonglong2* stgu = (const ulonglong2*)stg;

    int gidx = blockIdx.x * MAIN_THREADS + threadIdx.x;
    int e = g_perm[gidx];
    unsigned am = __ballot_sync(0xffffffffu, e >= 0);
    if (!am) return;                       // whole warp inactive (pad region)
    bool act = e >= 0;
    int s = act ? (e & 0xFFFFFF) : 0;
    int ldr = __ffs(am) - 1;
    int c = __shfl_sync(0xffffffffu, (e >> 24) & 7, ldr);   // warp-uniform bucket

    const ulonglong2* T1B = (const ulonglong2*)(sw + OFF_T1B) + c * 256;
    const ulonglong2* T1P = (const ulonglong2*)(sw + OFF_T1P) + c * 256;
    const u64* WOB = (const u64*)(sw + OFF_WOB) + c * 64;
    const u64* WOP = (const u64*)(sw + OFF_WOP) + c * 64;
    const ulonglong2* W2T = (const ulonglong2*)(sw + OFF_W2) + c * 512;
    const float* WO2 = sw + OFF_WO2 + c * 64;
    const float* M1B = sw + OFF_M1B + c * 8;
    const float* M1P = sw + OFF_M1P + c * 8;
    const float* B1B = sw + OFF_B1B + c * 8;
    const float* B1P = sw + OFF_B1P + c * 8;
    const float* B2 = sw + OFF_B2 + c * 64;

    float mob = fminf(mobv[s] * (7.0f / 255.0f), 1.0f);
    u64 accO = 0;
    float l1[16];
    u64 acc[8];

#pragma unroll
    for (int q = 0; q < 8; q++) acc[q] = 0;
    pass_stream(xb4, T1B, WOB, stg, stgu, lane, s, accO, acc);
#pragma unroll
    for (int q = 0; q < 8; q++)
        l1[q] = lo32(acc[q]) + hi32(acc[q]) + M1B[q] * mob + B1B[q];

#pragma unroll
    for (int q = 0; q < 8; q++) acc[q] = 0;
    pass_stream(xp4, T1P, WOP, stg, stgu, lane, s, accO, acc);
#pragma unroll
    for (int q = 0; q < 8; q++)
        l1[8 + q] = lo32(acc[q]) + hi32(acc[q]) + M1P[q] * mob + B1P[q];

    // layer-1 activations -> 16 packed pairs [sq(16), l1(16)] clipped to [0,1]
    const float F = 255.0f / 256.0f;
    u64 c2[16];
#pragma unroll
    for (int k = 0; k < 8; k++) {
        float q0 = fminf(l1[2 * k] * l1[2 * k] * F, 1.0f);
        float q1 = fminf(l1[2 * k + 1] * l1[2 * k + 1] * F, 1.0f);
        c2[k] = pk(q0, q1);
        float p0 = fminf(fmaxf(l1[2 * k], 0.0f), 1.0f);
        float p1 = fminf(fmaxf(l1[2 * k + 1], 0.0f), 1.0f);
        c2[8 + k] = pk(p0, p1);
    }

    // layer 2 fused with Wout[0:64]
    float osum = 0.0f;
#pragma unroll 4
    for (int o = 0; o < 64; o++) {
        const ulonglong2* wrow = W2T + o * 8;
        u64 ta = 0, tb = 0;
#pragma unroll
        for (int j = 0; j < 8; j++) {
            ulonglong2 w = wrow[j];
            ta = f2fma(w.x, c2[2 * j], ta);
            tb = f2fma(w.y, c2[2 * j + 1], tb);
        }
        float sv = lo32(ta) + hi32(ta) + lo32(tb) + hi32(tb) + B2[o];
        float av = fminf(fmaxf(sv, 0.0f), 1.0f);
        float vv = av * av * F;
        osum = fmaf(WO2[o], vv, osum);
    }

    float res = lo32(accO) + hi32(accO) + osum + sw[OFF_BOUT + c];
    if (act) out[s] = res;
}

// ---------------- launch ----------------
extern "C" void kernel_launch(void* const* d_in, const int* in_sizes, int n_in,
                              void* d_out, int out_size) {
    const float4* xb = (const float4*)d_in[0];
    const float4* xp = (const float4*)d_in[1];
    const float* mob = (const float*)d_in[2];
    const int* ply = (const int*)d_in[3];
    const float* W1b = (const float*)d_in[4];
    const float* b1b = (const float*)d_in[5];
    const float* W1pa = (const float*)d_in[6];
    const float* b1pa = (const float*)d_in[7];
    const float* W2 = (const float*)d_in[8];
    const float* b2 = (const float*)d_in[9];
    const float* Wout = (const float*)d_in[10];
    const float* bout = (const float*)d_in[11];
    float* out = (float*)d_out;
    int n = in_sizes[3];

    int nblk = (n + NB * 32 + MAIN_THREADS - 1) / MAIN_THREADS;
    int cap = nblk * MAIN_THREADS;
    if (cap > PERM_MAX) { cap = PERM_MAX; nblk = cap / MAIN_THREADS; }

    cudaFuncSetAttribute(k_main, cudaFuncAttributeMaxDynamicSharedMemorySize, SMEM_BYTES);

    k_init<<<nblk, MAIN_THREADS>>>(cap);
    k_pack<<<(WPK_F + 255) / 256, 256>>>(W1b, b1b, W1pa, b1pa, W2, b2, Wout, bout);
    k_count<<<(n + 511) / 512, 512>>>(ply, n);
    k_offsets<<<1, 1>>>();
    k_scatter<<<(n + 511) / 512, 512>>>(ply, n);
    k_main<<<nblk, MAIN_THREADS, SMEM_BYTES>>>(xb, xp, mob, out);
}

// round 5
// speedup vs baseline: 1.1774x; 1.1774x over previous
#include <cuda_runtime.h>
#include <cstdint>

typedef unsigned long long u64;

#define NB 6
#define BUCKET 10
#define MAX_BLK 520
#define PERM_CAP (MAX_BLK * 512)     // 266240
#define SPB 512                      // samples per main block
#define MAIN_THREADS 256

// ---- packed weight image (global) float offsets, per-bucket-contiguous ----
#define OFF_T1B 0                // [c][ip(64)][o(8)] pairs: 6*1024
#define OFF_T1P 6144
#define OFF_WOB 12288            // [c][ip(64)] pairs: 6*128
#define OFF_WOP 13056
#define OFF_W2  13824            // [c][o(64)][jj(16)] pairs: 6*2048
#define OFF_WO2 26112            // [c][64]
#define OFF_M1B 26496            // [c][8]
#define OFF_M1P 26544
#define OFF_B1B 26592
#define OFF_B1P 26640
#define OFF_B2  26688            // [c][64]
#define OFF_BOUT 27072           // [c]
#define WPK_F   27080

// ---- per-bucket smem weight layout (floats) ----
#define SB_T1B 0
#define SB_T1P 1024
#define SB_WOB 2048
#define SB_WOP 2176
#define SB_W2  2304
#define SB_WO2 4352
#define SB_M1B 4416
#define SB_M1P 4424
#define SB_B1B 4432
#define SB_B1P 4440
#define SB_B2  4448
#define SB_BOUT 4512
#define SB_END 4520              // 16B aligned

#define STAGE_F_PER_WARP 2048    // 2 groups x 32 rows x 8 float4
#define SMEM_FLOATS (SB_END + 8 * STAGE_F_PER_WARP)   // 20904
#define SMEM_BYTES  (SMEM_FLOATS * 4)                 // 83616

__device__ int   g_perm[PERM_CAP];
__device__ int   g_cnt[NB];        // zero-init; reset by k_main for next replay
__device__ int   g_cur[NB];        // reset by kA each replay
__device__ int   g_blkc[MAX_BLK];
__device__ float g_wpk[WPK_F];

// ---------------- f32x2 helpers ----------------
__device__ __forceinline__ u64 f2fma(u64 a, u64 b, u64 c) {
    u64 d;
    asm("fma.rn.f32x2 %0, %1, %2, %3;" : "=l"(d) : "l"(a), "l"(b), "l"(c));
    return d;
}
__device__ __forceinline__ float lo32(u64 a) { return __uint_as_float((unsigned)a); }
__device__ __forceinline__ float hi32(u64 a) { return __uint_as_float((unsigned)(a >> 32)); }
__device__ __forceinline__ u64 pk(float lo, float hi) {
    u64 r;
    asm("mov.b64 %0, {%1, %2};" : "=l"(r) : "f"(lo), "f"(hi));
    return r;
}

// ---------------- kA: pack weights + histogram + reset g_cur ----------------
__global__ void kA(const float* __restrict__ W1b, const float* __restrict__ b1b,
                   const float* __restrict__ W1pa, const float* __restrict__ b1pa,
                   const float* __restrict__ W2, const float* __restrict__ b2,
                   const float* __restrict__ Wout, const float* __restrict__ bout,
                   const int* __restrict__ ply, int n) {
    __shared__ int h[NB];
    int tid = threadIdx.x;
    if (tid < NB) h[tid] = 0;
    __syncthreads();
    int i = blockIdx.x * blockDim.x + tid;

    if (i < WPK_F) {
        float v = 0.0f;
        if (i < OFF_T1P) {
            int hh = i & 1, t = i >> 1;
            int o = t & 7, ip = (t >> 3) & 63, c = t >> 9;
            v = W1b[(c * 8 + o) * 129 + 2 * ip + hh];
        } else if (i < OFF_WOB) {
            int j = i - OFF_T1P;
            int hh = j & 1, t = j >> 1;
            int o = t & 7, ip = (t >> 3) & 63, c = t >> 9;
            v = W1pa[(c * 8 + o) * 129 + 2 * ip + hh];
        } else if (i < OFF_WOP) {
            int j = i - OFF_WOB;
            int hh = j & 1, t = j >> 1;
            int ip = t & 63, c = t >> 6;
            v = Wout[c * 320 + 64 + 2 * ip + hh];
        } else if (i < OFF_W2) {
            int j = i - OFF_WOP;
            int hh = j & 1, t = j >> 1;
            int ip = t & 63, c = t >> 6;
            v = Wout[c * 320 + 192 + 2 * ip + hh];
        } else if (i < OFF_WO2) {
            int j = i - OFF_W2;
            int hh = j & 1, t = j >> 1;
            int jj = t & 15, o = (t >> 4) & 63, c = t >> 10;
            v = W2[(c * 64 + o) * 32 + 2 * jj + hh];
        } else if (i < OFF_M1B) {
            int j = i - OFF_WO2;
            int o = j & 63, c = j >> 6;
            v = Wout[c * 320 + o];
        } else if (i < OFF_M1P) {
            int j = i - OFF_M1B;
            int o = j & 7, c = j >> 3;
            v = W1b[(c * 8 + o) * 129 + 128];
        } else if (i < OFF_B1B) {
            int j = i - OFF_M1P;
            int o = j & 7, c = j >> 3;
            v = W1pa[(c * 8 + o) * 129 + 128];
        } else if (i < OFF_B1P) {
            v = b1b[i - OFF_B1B];
        } else if (i < OFF_B2) {
            v = b1pa[i - OFF_B1P];
        } else if (i < OFF_BOUT) {
            v = b2[i - OFF_B2];
        } else {
            v = bout[i - OFF_BOUT];
        }
        g_wpk[i] = v;
    }
    if (i < NB) g_cur[i] = 0;
    if (i < n) {
        int c = ply[i] / BUCKET;
        c = min(max(c, 0), NB - 1);
        atomicAdd(&h[c], 1);
    }
    __syncthreads();
    if (tid < NB && h[tid]) atomicAdd(&g_cnt[tid], h[tid]);
}

// ---------------- kB: scatter + pad-fill + blkc ----------------
__global__ void kB(const int* __restrict__ ply, int n, int nmb) {
    // offsets (each thread computes locally; regions padded to SPB multiples)
    int start[NB], padc[NB];
    int base = 0;
    int cnt_l[NB];
#pragma unroll
    for (int c = 0; c < NB; c++) {
        cnt_l[c] = g_cnt[c];
        start[c] = base;
        padc[c] = ((cnt_l[c] + SPB - 1) / SPB) * SPB;
        base += padc[c];
    }
    int total = base;

    int i = blockIdx.x * blockDim.x + threadIdx.x;

    // scatter (warp-aggregated)
    int c = -1;
    if (i < n) {
        c = ply[i] / BUCKET;
        c = min(max(c, 0), NB - 1);
    }
    unsigned lane = threadIdx.x & 31;
#pragma unroll
    for (int cc = 0; cc < NB; cc++) {
        unsigned m = __ballot_sync(0xffffffffu, c == cc);
        if (c == cc) {
            int leader = __ffs(m) - 1;
            int cntw = __popc(m);
            int rank = __popc(m & ((1u << lane) - 1u));
            int pos = 0;
            if ((int)lane == leader) pos = atomicAdd(&g_cur[cc], cntw);
            pos = __shfl_sync(m, pos, leader);
            g_perm[start[cc] + pos + rank] = i;
        }
    }

    // pad-fill: slot role
    if (i < total) {
#pragma unroll
        for (int cc = 0; cc < NB; cc++) {
            if (i >= start[cc] + cnt_l[cc] && i < start[cc] + padc[cc])
                g_perm[i] = -1;
        }
    }

    // per-main-block bucket id
    if (blockIdx.x == 0) {
        for (int j = threadIdx.x; j < nmb; j += blockDim.x) {
            int b = j * SPB;
            int bc = -1;
#pragma unroll
            for (int cc = 0; cc < NB; cc++) {
                if (b >= start[cc] && b < start[cc] + padc[cc]) bc = cc;
            }
            if (b >= total) bc = -1;
            g_blkc[j] = bc;
        }
    }
}

// ---------------- main kernel ----------------
// 256 threads, 8 warps; each warp handles 2 groups of 32 samples (S=2).
// Weights loaded once per warp-pass, applied to both groups.
__device__ __forceinline__ void pass2(
    const float4* __restrict__ x4, const ulonglong2* __restrict__ T1,
    const u64* __restrict__ WO, float4* stg, const ulonglong2* stgu,
    int lane, int r, int ch, int s0, int s1,
    u64 accO[2], u64 acc0[8], u64 acc1[8]) {
#pragma unroll
    for (int T = 0; T < 4; T++) {
        __syncwarp();
#pragma unroll
        for (int k = 0; k < 8; k++) {
            int rr = k * 4 + r;
            int idx = rr * 8 + (ch ^ (rr & 7));
            int row0 = __shfl_sync(0xffffffffu, s0, rr);
            stg[idx] = x4[(size_t)row0 * 32 + T * 8 + ch];
            int row1 = __shfl_sync(0xffffffffu, s1, rr);
            stg[256 + idx] = x4[(size_t)row1 * 32 + T * 8 + ch];
        }
        __syncwarp();
#pragma unroll
        for (int t = 0; t < 8; t++) {
            int ip0 = T * 16 + 2 * t;
            int ip1 = ip0 + 1;
            ulonglong2 wA0 = T1[ip0 * 4 + 0], wB0 = T1[ip0 * 4 + 1];
            ulonglong2 wC0 = T1[ip0 * 4 + 2], wD0 = T1[ip0 * 4 + 3];
            ulonglong2 wA1 = T1[ip1 * 4 + 0], wB1 = T1[ip1 * 4 + 1];
            ulonglong2 wC1 = T1[ip1 * 4 + 2], wD1 = T1[ip1 * 4 + 3];
            u64 wo0 = WO[ip0], wo1 = WO[ip1];
            int sidx = lane * 8 + (t ^ (lane & 7));
            {
                ulonglong2 xv = stgu[sidx];
                acc0[0] = f2fma(wA0.x, xv.x, acc0[0]);
                acc0[1] = f2fma(wA0.y, xv.x, acc0[1]);
                acc0[2] = f2fma(wB0.x, xv.x, acc0[2]);
                acc0[3] = f2fma(wB0.y, xv.x, acc0[3]);
                acc0[4] = f2fma(wC0.x, xv.x, acc0[4]);
                acc0[5] = f2fma(wC0.y, xv.x, acc0[5]);
                acc0[6] = f2fma(wD0.x, xv.x, acc0[6]);
                acc0[7] = f2fma(wD0.y, xv.x, acc0[7]);
                accO[0] = f2fma(wo0, xv.x, accO[0]);
                acc0[0] = f2fma(wA1.x, xv.y, acc0[0]);
                acc0[1] = f2fma(wA1.y, xv.y, acc0[1]);
                acc0[2] = f2fma(wB1.x, xv.y, acc0[2]);
                acc0[3] = f2fma(wB1.y, xv.y, acc0[3]);
                acc0[4] = f2fma(wC1.x, xv.y, acc0[4]);
                acc0[5] = f2fma(wC1.y, xv.y, acc0[5]);
                acc0[6] = f2fma(wD1.x, xv.y, acc0[6]);
                acc0[7] = f2fma(wD1.y, xv.y, acc0[7]);
                accO[0] = f2fma(wo1, xv.y, accO[0]);
            }
            {
                ulonglong2 xv = stgu[256 + sidx];
                acc1[0] = f2fma(wA0.x, xv.x, acc1[0]);
                acc1[1] = f2fma(wA0.y, xv.x, acc1[1]);
                acc1[2] = f2fma(wB0.x, xv.x, acc1[2]);
                acc1[3] = f2fma(wB0.y, xv.x, acc1[3]);
                acc1[4] = f2fma(wC0.x, xv.x, acc1[4]);
                acc1[5] = f2fma(wC0.y, xv.x, acc1[5]);
                acc1[6] = f2fma(wD0.x, xv.x, acc1[6]);
                acc1[7] = f2fma(wD0.y, xv.x, acc1[7]);
                accO[1] = f2fma(wo0, xv.x, accO[1]);
                acc1[0] = f2fma(wA1.x, xv.y, acc1[0]);
                acc1[1] = f2fma(wA1.y, xv.y, acc1[1]);
                acc1[2] = f2fma(wB1.x, xv.y, acc1[2]);
                acc1[3] = f2fma(wB1.y, xv.y, acc1[3]);
                acc1[4] = f2fma(wC1.x, xv.y, acc1[4]);
                acc1[5] = f2fma(wC1.y, xv.y, acc1[5]);
                acc1[6] = f2fma(wD1.x, xv.y, acc1[6]);
                acc1[7] = f2fma(wD1.y, xv.y, acc1[7]);
                accO[1] = f2fma(wo1, xv.y, accO[1]);
            }
        }
    }
}

__global__ __launch_bounds__(MAIN_THREADS, 2)
void k_main(const float4* __restrict__ xb4, const float4* __restrict__ xp4,
            const float* __restrict__ mobv, float* __restrict__ out) {
    if (blockIdx.x == 0 && threadIdx.x < NB) g_cnt[threadIdx.x] = 0;  // for next replay

    int c = g_blkc[blockIdx.x];
    if (c < 0) return;                 // whole block beyond data (uniform)

    extern __shared__ float sw[];
    // copy this bucket's weights into smem
    {
        const int tid = threadIdx.x;
        const float4* s1 = (const float4*)(g_wpk + OFF_T1B + c * 1024);
        const float4* s2 = (const float4*)(g_wpk + OFF_T1P + c * 1024);
        float4* d1 = (float4*)(sw + SB_T1B);
        float4* d2 = (float4*)(sw + SB_T1P);
        for (int i = tid; i < 256; i += MAIN_THREADS) { d1[i] = s1[i]; d2[i] = s2[i]; }
        const float4* s5 = (const float4*)(g_wpk + OFF_W2 + c * 2048);
        float4* d5 = (float4*)(sw + SB_W2);
        for (int i = tid; i < 512; i += MAIN_THREADS) d5[i] = s5[i];
        if (tid < 32) {
            ((float4*)(sw + SB_WOB))[tid] = ((const float4*)(g_wpk + OFF_WOB + c * 128))[tid];
            ((float4*)(sw + SB_WOP))[tid] = ((const float4*)(g_wpk + OFF_WOP + c * 128))[tid];
        } else if (tid < 64) {
            int j = tid - 32;
            if (j < 16) ((float4*)(sw + SB_WO2))[j] = ((const float4*)(g_wpk + OFF_WO2 + c * 64))[j];
        } else if (tid < 96) {
            int j = tid - 64;
            if (j < 16) ((float4*)(sw + SB_B2))[j] = ((const float4*)(g_wpk + OFF_B2 + c * 64))[j];
        } else if (tid < 128) {
            int j = tid - 96;
            if (j < 8) {
                sw[SB_M1B + j] = g_wpk[OFF_M1B + c * 8 + j];
                sw[SB_M1P + j] = g_wpk[OFF_M1P + c * 8 + j];
                sw[SB_B1B + j] = g_wpk[OFF_B1B + c * 8 + j];
                sw[SB_B1P + j] = g_wpk[OFF_B1P + c * 8 + j];
            }
            if (j == 0) sw[SB_BOUT] = g_wpk[OFF_BOUT + c];
        }
    }
    __syncthreads();

    const int lane = threadIdx.x & 31;
    const int wid = threadIdx.x >> 5;
    const int r = lane >> 3, ch = lane & 7;
    float4* stg = (float4*)(sw + SB_END) + wid * (STAGE_F_PER_WARP / 4);
    const ulonglong2* stgu = (const ulonglong2*)stg;

    int base = blockIdx.x * SPB + wid * 64 + lane;
    int e0 = g_perm[base];
    int e1 = g_perm[base + 32];
    bool a0 = e0 >= 0, a1 = e1 >= 0;
    int s0 = a0 ? e0 : 0;
    int s1 = a1 ? e1 : 0;

    const ulonglong2* T1B = (const ulonglong2*)(sw + SB_T1B);
    const ulonglong2* T1P = (const ulonglong2*)(sw + SB_T1P);
    const u64* WOB = (const u64*)(sw + SB_WOB);
    const u64* WOP = (const u64*)(sw + SB_WOP);
    const ulonglong2* W2T = (const ulonglong2*)(sw + SB_W2);
    const float* WO2 = sw + SB_WO2;
    const float* M1B = sw + SB_M1B;
    const float* M1P = sw + SB_M1P;
    const float* B1B = sw + SB_B1B;
    const float* B1P = sw + SB_B1P;
    const float* B2 = sw + SB_B2;

    float mob0 = fminf(mobv[s0] * (7.0f / 255.0f), 1.0f);
    float mob1 = fminf(mobv[s1] * (7.0f / 255.0f), 1.0f);

    u64 accO[2] = {0, 0};
    u64 acc0[8], acc1[8];
    float l1a[16], l1b[16];

#pragma unroll
    for (int q = 0; q < 8; q++) { acc0[q] = 0; acc1[q] = 0; }
    pass2(xb4, T1B, WOB, stg, stgu, lane, r, ch, s0, s1, accO, acc0, acc1);
#pragma unroll
    for (int q = 0; q < 8; q++) {
        l1a[q] = lo32(acc0[q]) + hi32(acc0[q]) + M1B[q] * mob0 + B1B[q];
        l1b[q] = lo32(acc1[q]) + hi32(acc1[q]) + M1B[q] * mob1 + B1B[q];
    }

#pragma unroll
    for (int q = 0; q < 8; q++) { acc0[q] = 0; acc1[q] = 0; }
    pass2(xp4, T1P, WOP, stg, stgu, lane, r, ch, s0, s1, accO, acc0, acc1);
#pragma unroll
    for (int q = 0; q < 8; q++) {
        l1a[8 + q] = lo32(acc0[q]) + hi32(acc0[q]) + M1P[q] * mob0 + B1P[q];
        l1b[8 + q] = lo32(acc1[q]) + hi32(acc1[q]) + M1P[q] * mob1 + B1P[q];
    }

    // activations -> packed pairs [sq(16), l1(16)] clipped to [0,1]
    const float F = 255.0f / 256.0f;
    u64 c2a[16], c2b[16];
#pragma unroll
    for (int k = 0; k < 8; k++) {
        c2a[k] = pk(fminf(l1a[2 * k] * l1a[2 * k] * F, 1.0f),
                    fminf(l1a[2 * k + 1] * l1a[2 * k + 1] * F, 1.0f));
        c2a[8 + k] = pk(fminf(fmaxf(l1a[2 * k], 0.0f), 1.0f),
                        fminf(fmaxf(l1a[2 * k + 1], 0.0f), 1.0f));
        c2b[k] = pk(fminf(l1b[2 * k] * l1b[2 * k] * F, 1.0f),
                    fminf(l1b[2 * k + 1] * l1b[2 * k + 1] * F, 1.0f));
        c2b[8 + k] = pk(fminf(fmaxf(l1b[2 * k], 0.0f), 1.0f),
                        fminf(fmaxf(l1b[2 * k + 1], 0.0f), 1.0f));
    }

    // layer2 fused with Wout[0:64]; W2 loads shared across both groups
    float osum0 = 0.0f, osum1 = 0.0f;
#pragma unroll 2
    for (int o = 0; o < 64; o++) {
        const ulonglong2* wrow = W2T + o * 8;
        u64 ta0 = 0, tb0 = 0, ta1 = 0, tb1 = 0;
#pragma unroll
        for (int j = 0; j < 8; j++) {
            ulonglong2 w = wrow[j];
            ta0 = f2fma(w.x, c2a[2 * j], ta0);
            tb0 = f2fma(w.y, c2a[2 * j + 1], tb0);
            ta1 = f2fma(w.x, c2b[2 * j], ta1);
            tb1 = f2fma(w.y, c2b[2 * j + 1], tb1);
        }
        float wo = WO2[o], bb = B2[o];
        float sv0 = lo32(ta0) + hi32(ta0) + lo32(tb0) + hi32(tb0) + bb;
        float av0 = fminf(fmaxf(sv0, 0.0f), 1.0f);
        osum0 = fmaf(wo, av0 * av0 * F, osum0);
        float sv1 = lo32(ta1) + hi32(ta1) + lo32(tb1) + hi32(tb1) + bb;
        float av1 = fminf(fmaxf(sv1, 0.0f), 1.0f);
        osum1 = fmaf(wo, av1 * av1 * F, osum1);
    }

    float bo = sw[SB_BOUT];
    if (a0) out[s0] = lo32(accO[0]) + hi32(accO[0]) + osum0 + bo;
    if (a1) out[s1] = lo32(accO[1]) + hi32(accO[1]) + osum1 + bo;
}

// ---------------- launch ----------------
extern "C" void kernel_launch(void* const* d_in, const int* in_sizes, int n_in,
                              void* d_out, int out_size) {
    const float4* xb = (const float4*)d_in[0];
    const float4* xp = (const float4*)d_in[1];
    const float* mob = (const float*)d_in[2];
    const int* ply = (const int*)d_in[3];
    const float* W1b = (const float*)d_in[4];
    const float* b1b = (const float*)d_in[5];
    const float* W1pa = (const float*)d_in[6];
    const float* b1pa = (const float*)d_in[7];
    const float* W2 = (const float*)d_in[8];
    const float* b2 = (const float*)d_in[9];
    const float* Wout = (const float*)d_in[10];
    const float* bout = (const float*)d_in[11];
    float* out = (float*)d_out;
    int n = in_sizes[3];

    int nmb = (n + SPB - 1) / SPB + NB;
    if (nmb > MAX_BLK) nmb = MAX_BLK;

    cudaFuncSetAttribute(k_main, cudaFuncAttributeMaxDynamicSharedMemorySize, SMEM_BYTES);

    kA<<<(n + 255) / 256, 256>>>(W1b, b1b, W1pa, b1pa, W2, b2, Wout, bout, ply, n);
    kB<<<(nmb * SPB + 255) / 256, 256>>>(ply, n, nmb);
    k_main<<<nmb, MAIN_THREADS, SMEM_BYTES>>>(xb, xp, mob, out);
}

// round 6
// speedup vs baseline: 1.5419x; 1.3096x over previous
#include <cuda_runtime.h>
#include <cstdint>

typedef unsigned long long u64;

#define NB 6
#define BUCKET 10
#define MAX_BLK 520
#define PERM_CAP (MAX_BLK * 512)     // 266240
#define SPB 512                      // samples per main block
#define MAIN_THREADS 256

// ---- packed weight image (global) float offsets, per-bucket-contiguous ----
#define OFF_T1B 0                // [c][ip(64)][o(8)] pairs: 6*1024
#define OFF_T1P 6144
#define OFF_WOB 12288            // [c][ip(64)] pairs: 6*128
#define OFF_WOP 13056
#define OFF_W2  13824            // [c][o(64)][jj(16)] pairs: 6*2048
#define OFF_WO2 26112            // [c][64]
#define OFF_M1B 26496            // [c][8]
#define OFF_M1P 26544
#define OFF_B1B 26592
#define OFF_B1P 26640
#define OFF_B2  26688            // [c][64]
#define OFF_BOUT 27072           // [c]
#define WPK_F   27080

// ---- per-bucket smem weight layout (floats) ----
#define SB_T1B 0
#define SB_T1P 1024
#define SB_WOB 2048
#define SB_WOP 2176
#define SB_W2  2304
#define SB_WO2 4352
#define SB_M1B 4416
#define SB_M1P 4424
#define SB_B1B 4432
#define SB_B1P 4440
#define SB_B2  4448
#define SB_BOUT 4512
#define SB_END 4520              // 16B aligned (18080 bytes)

// stage: per warp, 2 buffers x 4KB (32 rows x 128B; both groups in the 8 cols)
#define STAGE_F_PER_WARP 2048    // floats (8KB)
#define SMEM_FLOATS (SB_END + 8 * STAGE_F_PER_WARP)   // 20904
#define SMEM_BYTES  (SMEM_FLOATS * 4)                 // 83616

__device__ int   g_perm[PERM_CAP];
__device__ int   g_cnt[NB];        // zero-init; reset by k_main for next replay
__device__ int   g_cur[NB];        // reset by kA each replay
__device__ int   g_blkc[MAX_BLK];
__device__ float g_wpk[WPK_F];

// ---------------- helpers ----------------
__device__ __forceinline__ u64 f2fma(u64 a, u64 b, u64 c) {
    u64 d;
    asm("fma.rn.f32x2 %0, %1, %2, %3;" : "=l"(d) : "l"(a), "l"(b), "l"(c));
    return d;
}
__device__ __forceinline__ float lo32(u64 a) { return __uint_as_float((unsigned)a); }
__device__ __forceinline__ float hi32(u64 a) { return __uint_as_float((unsigned)(a >> 32)); }
__device__ __forceinline__ u64 pk(float lo, float hi) {
    u64 r;
    asm("mov.b64 %0, {%1, %2};" : "=l"(r) : "f"(lo), "f"(hi));
    return r;
}
#define CP16(saddr, gptr) \
    asm volatile("cp.async.cg.shared.global [%0], [%1], 16;" :: "r"(saddr), "l"(gptr))
#define CPCOMMIT() asm volatile("cp.async.commit_group;")
#define CPWAIT(n)  asm volatile("cp.async.wait_group %0;" :: "n"(n))

// ---------------- kA: pack weights + histogram + reset g_cur ----------------
__global__ void kA(const float* __restrict__ W1b, const float* __restrict__ b1b,
                   const float* __restrict__ W1pa, const float* __restrict__ b1pa,
                   const float* __restrict__ W2, const float* __restrict__ b2,
                   const float* __restrict__ Wout, const float* __restrict__ bout,
                   const int* __restrict__ ply, int n) {
    __shared__ int h[NB];
    int tid = threadIdx.x;
    if (tid < NB) h[tid] = 0;
    __syncthreads();
    int i = blockIdx.x * blockDim.x + tid;

    if (i < WPK_F) {
        float v = 0.0f;
        if (i < OFF_T1P) {
            int hh = i & 1, t = i >> 1;
            int o = t & 7, ip = (t >> 3) & 63, c = t >> 9;
            v = W1b[(c * 8 + o) * 129 + 2 * ip + hh];
        } else if (i < OFF_WOB) {
            int j = i - OFF_T1P;
            int hh = j & 1, t = j >> 1;
            int o = t & 7, ip = (t >> 3) & 63, c = t >> 9;
            v = W1pa[(c * 8 + o) * 129 + 2 * ip + hh];
        } else if (i < OFF_WOP) {
            int j = i - OFF_WOB;
            int hh = j & 1, t = j >> 1;
            int ip = t & 63, c = t >> 6;
            v = Wout[c * 320 + 64 + 2 * ip + hh];
        } else if (i < OFF_W2) {
            int j = i - OFF_WOP;
            int hh = j & 1, t = j >> 1;
            int ip = t & 63, c = t >> 6;
            v = Wout[c * 320 + 192 + 2 * ip + hh];
        } else if (i < OFF_WO2) {
            int j = i - OFF_W2;
            int hh = j & 1, t = j >> 1;
            int jj = t & 15, o = (t >> 4) & 63, c = t >> 10;
            v = W2[(c * 64 + o) * 32 + 2 * jj + hh];
        } else if (i < OFF_M1B) {
            int j = i - OFF_WO2;
            int o = j & 63, c = j >> 6;
            v = Wout[c * 320 + o];
        } else if (i < OFF_M1P) {
            int j = i - OFF_M1B;
            int o = j & 7, c = j >> 3;
            v = W1b[(c * 8 + o) * 129 + 128];
        } else if (i < OFF_B1B) {
            int j = i - OFF_M1P;
            int o = j & 7, c = j >> 3;
            v = W1pa[(c * 8 + o) * 129 + 128];
        } else if (i < OFF_B1P) {
            v = b1b[i - OFF_B1B];
        } else if (i < OFF_B2) {
            v = b1pa[i - OFF_B1P];
        } else if (i < OFF_BOUT) {
            v = b2[i - OFF_B2];
        } else {
            v = bout[i - OFF_BOUT];
        }
        g_wpk[i] = v;
    }
    if (i < NB) g_cur[i] = 0;
    if (i < n) {
        int c = ply[i] / BUCKET;
        c = min(max(c, 0), NB - 1);
        atomicAdd(&h[c], 1);
    }
    __syncthreads();
    if (tid < NB && h[tid]) atomicAdd(&g_cnt[tid], h[tid]);
}

// ---------------- kB: scatter + pad-fill + blkc ----------------
__global__ void kB(const int* __restrict__ ply, int n, int nmb) {
    int start[NB], padc[NB];
    int base = 0;
    int cnt_l[NB];
#pragma unroll
    for (int c = 0; c < NB; c++) {
        cnt_l[c] = g_cnt[c];
        start[c] = base;
        padc[c] = ((cnt_l[c] + SPB - 1) / SPB) * SPB;
        base += padc[c];
    }
    int total = base;

    int i = blockIdx.x * blockDim.x + threadIdx.x;

    int c = -1;
    if (i < n) {
        c = ply[i] / BUCKET;
        c = min(max(c, 0), NB - 1);
    }
    unsigned lane = threadIdx.x & 31;
#pragma unroll
    for (int cc = 0; cc < NB; cc++) {
        unsigned m = __ballot_sync(0xffffffffu, c == cc);
        if (c == cc) {
            int leader = __ffs(m) - 1;
            int cntw = __popc(m);
            int rank = __popc(m & ((1u << lane) - 1u));
            int pos = 0;
            if ((int)lane == leader) pos = atomicAdd(&g_cur[cc], cntw);
            pos = __shfl_sync(m, pos, leader);
            g_perm[start[cc] + pos + rank] = i;
        }
    }

    if (i < total) {
#pragma unroll
        for (int cc = 0; cc < NB; cc++) {
            if (i >= start[cc] + cnt_l[cc] && i < start[cc] + padc[cc])
                g_perm[i] = -1;
        }
    }

    if (blockIdx.x == 0) {
        for (int j = threadIdx.x; j < nmb; j += blockDim.x) {
            int b = j * SPB;
            int bc = -1;
#pragma unroll
            for (int cc = 0; cc < NB; cc++) {
                if (b >= start[cc] && b < start[cc] + padc[cc]) bc = cc;
            }
            if (b >= total) bc = -1;
            g_blkc[j] = bc;
        }
    }
}

// ---------------- main kernel ----------------
// 256 threads, 8 warps; each warp handles 2 groups of 32 samples.
// x staged via cp.async double-buffered pipeline (8 chunks of 64B/row per pass).
// Stage layout per buffer: offset(g,row,col) = row*128B + (((g*4+col) ^ (row&7)) * 16B)

__device__ __forceinline__ void prefetch_chunk(
    const float4* __restrict__ src, int T, uint32_t sbuf,
    int lane, int s0, int s1) {
    const int rl = lane & 7;
    const int col = lane >> 3;             // 0..3
#pragma unroll
    for (int k = 0; k < 4; k++) {
        int row = k * 8 + rl;
        int r0 = __shfl_sync(0xffffffffu, s0, row);
        const float4* gp0 = src + (size_t)r0 * 32 + T * 4 + col;
        CP16(sbuf + row * 128 + ((col ^ rl) << 4), gp0);
        int r1 = __shfl_sync(0xffffffffu, s1, row);
        const float4* gp1 = src + (size_t)r1 * 32 + T * 4 + col;
        CP16(sbuf + row * 128 + (((4 + col) ^ rl) << 4), gp1);
    }
    CPCOMMIT();
}

__device__ __forceinline__ void compute_chunk(
    const float* __restrict__ buf, int T,
    const ulonglong2* __restrict__ T1, const u64* __restrict__ WO,
    int lane, u64& aO0, u64& aO1, u64 acc0[8], u64 acc1[8]) {
    const char* bc = (const char*)buf + lane * 128;
    const int rl = lane & 7;
#pragma unroll
    for (int j = 0; j < 4; j++) {
        ulonglong2 xv0 = *(const ulonglong2*)(bc + ((j ^ rl) << 4));
        ulonglong2 xv1 = *(const ulonglong2*)(bc + (((4 + j) ^ rl) << 4));
        int ip0 = T * 8 + 2 * j;
        int ip1 = ip0 + 1;
        ulonglong2 wA0 = T1[ip0 * 4 + 0], wB0 = T1[ip0 * 4 + 1];
        ulonglong2 wC0 = T1[ip0 * 4 + 2], wD0 = T1[ip0 * 4 + 3];
        ulonglong2 wA1 = T1[ip1 * 4 + 0], wB1 = T1[ip1 * 4 + 1];
        ulonglong2 wC1 = T1[ip1 * 4 + 2], wD1 = T1[ip1 * 4 + 3];
        u64 wo0 = WO[ip0], wo1 = WO[ip1];
        // group 0
        acc0[0] = f2fma(wA0.x, xv0.x, acc0[0]);
        acc0[1] = f2fma(wA0.y, xv0.x, acc0[1]);
        acc0[2] = f2fma(wB0.x, xv0.x, acc0[2]);
        acc0[3] = f2fma(wB0.y, xv0.x, acc0[3]);
        acc0[4] = f2fma(wC0.x, xv0.x, acc0[4]);
        acc0[5] = f2fma(wC0.y, xv0.x, acc0[5]);
        acc0[6] = f2fma(wD0.x, xv0.x, acc0[6]);
        acc0[7] = f2fma(wD0.y, xv0.x, acc0[7]);
        aO0 = f2fma(wo0, xv0.x, aO0);
        acc0[0] = f2fma(wA1.x, xv0.y, acc0[0]);
        acc0[1] = f2fma(wA1.y, xv0.y, acc0[1]);
        acc0[2] = f2fma(wB1.x, xv0.y, acc0[2]);
        acc0[3] = f2fma(wB1.y, xv0.y, acc0[3]);
        acc0[4] = f2fma(wC1.x, xv0.y, acc0[4]);
        acc0[5] = f2fma(wC1.y, xv0.y, acc0[5]);
        acc0[6] = f2fma(wD1.x, xv0.y, acc0[6]);
        acc0[7] = f2fma(wD1.y, xv0.y, acc0[7]);
        aO0 = f2fma(wo1, xv0.y, aO0);
        // group 1
        acc1[0] = f2fma(wA0.x, xv1.x, acc1[0]);
        acc1[1] = f2fma(wA0.y, xv1.x, acc1[1]);
        acc1[2] = f2fma(wB0.x, xv1.x, acc1[2]);
        acc1[3] = f2fma(wB0.y, xv1.x, acc1[3]);
        acc1[4] = f2fma(wC0.x, xv1.x, acc1[4]);
        acc1[5] = f2fma(wC0.y, xv1.x, acc1[5]);
        acc1[6] = f2fma(wD0.x, xv1.x, acc1[6]);
        acc1[7] = f2fma(wD0.y, xv1.x, acc1[7]);
        aO1 = f2fma(wo0, xv1.x, aO1);
        acc1[0] = f2fma(wA1.x, xv1.y, acc1[0]);
        acc1[1] = f2fma(wA1.y, xv1.y, acc1[1]);
        acc1[2] = f2fma(wB1.x, xv1.y, acc1[2]);
        acc1[3] = f2fma(wB1.y, xv1.y, acc1[3]);
        acc1[4] = f2fma(wC1.x, xv1.y, acc1[4]);
        acc1[5] = f2fma(wC1.y, xv1.y, acc1[5]);
        acc1[6] = f2fma(wD1.x, xv1.y, acc1[6]);
        acc1[7] = f2fma(wD1.y, xv1.y, acc1[7]);
        aO1 = f2fma(wo1, xv1.y, aO1);
    }
}

__global__ __launch_bounds__(MAIN_THREADS, 2)
void k_main(const float4* __restrict__ xb4, const float4* __restrict__ xp4,
            const float* __restrict__ mobv, float* __restrict__ out) {
    if (blockIdx.x == 0 && threadIdx.x < NB) g_cnt[threadIdx.x] = 0;  // next replay

    int c = g_blkc[blockIdx.x];
    if (c < 0) return;

    extern __shared__ float sw[];
    const int lane = threadIdx.x & 31;
    const int wid = threadIdx.x >> 5;
    float* stage = sw + SB_END + wid * STAGE_F_PER_WARP;
    uint32_t stg_s = (uint32_t)__cvta_generic_to_shared(stage);

    // sample ids first, then prologue prefetch (overlaps weight copy below)
    int base = blockIdx.x * SPB + wid * 64 + lane;
    int e0 = g_perm[base];
    int e1 = g_perm[base + 32];
    bool a0 = e0 >= 0, a1 = e1 >= 0;
    int s0 = a0 ? e0 : 0;
    int s1 = a1 ? e1 : 0;
    float mv0 = __ldg(mobv + s0);
    float mv1 = __ldg(mobv + s1);
    prefetch_chunk(xb4, 0, stg_s, lane, s0, s1);   // chunk0 -> buf0

    // copy this bucket's weights into smem
    {
        const int tid = threadIdx.x;
        const float4* w1 = (const float4*)(g_wpk + OFF_T1B + c * 1024);
        const float4* w2 = (const float4*)(g_wpk + OFF_T1P + c * 1024);
        float4* d1 = (float4*)(sw + SB_T1B);
        float4* d2 = (float4*)(sw + SB_T1P);
        for (int i = tid; i < 256; i += MAIN_THREADS) { d1[i] = w1[i]; d2[i] = w2[i]; }
        const float4* w5 = (const float4*)(g_wpk + OFF_W2 + c * 2048);
        float4* d5 = (float4*)(sw + SB_W2);
        for (int i = tid; i < 512; i += MAIN_THREADS) d5[i] = w5[i];
        if (tid < 32) {
            ((float4*)(sw + SB_WOB))[tid] = ((const float4*)(g_wpk + OFF_WOB + c * 128))[tid];
            ((float4*)(sw + SB_WOP))[tid] = ((const float4*)(g_wpk + OFF_WOP + c * 128))[tid];
        } else if (tid < 64) {
            int j = tid - 32;
            if (j < 16) ((float4*)(sw + SB_WO2))[j] = ((const float4*)(g_wpk + OFF_WO2 + c * 64))[j];
        } else if (tid < 96) {
            int j = tid - 64;
            if (j < 16) ((float4*)(sw + SB_B2))[j] = ((const float4*)(g_wpk + OFF_B2 + c * 64))[j];
        } else if (tid < 128) {
            int j = tid - 96;
            if (j < 8) {
                sw[SB_M1B + j] = g_wpk[OFF_M1B + c * 8 + j];
                sw[SB_M1P + j] = g_wpk[OFF_M1P + c * 8 + j];
                sw[SB_B1B + j] = g_wpk[OFF_B1B + c * 8 + j];
                sw[SB_B1P + j] = g_wpk[OFF_B1P + c * 8 + j];
            }
            if (j == 0) sw[SB_BOUT] = g_wpk[OFF_BOUT + c];
        }
    }
    __syncthreads();

    const ulonglong2* T1B = (const ulonglong2*)(sw + SB_T1B);
    const ulonglong2* T1P = (const ulonglong2*)(sw + SB_T1P);
    const u64* WOB = (const u64*)(sw + SB_WOB);
    const u64* WOP = (const u64*)(sw + SB_WOP);
    const ulonglong2* W2T = (const ulonglong2*)(sw + SB_W2);
    const float* WO2 = sw + SB_WO2;
    const float* M1B = sw + SB_M1B;
    const float* M1P = sw + SB_M1P;
    const float* B1B = sw + SB_B1B;
    const float* B1P = sw + SB_B1P;
    const float* B2 = sw + SB_B2;

    float mob0 = fminf(mv0 * (7.0f / 255.0f), 1.0f);
    float mob1 = fminf(mv1 * (7.0f / 255.0f), 1.0f);

    u64 aO0 = 0, aO1 = 0;
    u64 acc0[8], acc1[8];
    float l1a[16], l1b[16];

#pragma unroll
    for (int q = 0; q < 8; q++) { acc0[q] = 0; acc1[q] = 0; }

    // ---- pass 1 (x_base), prefetching next chunk each iter; at T=7 prefetch xpa chunk0
#pragma unroll 2
    for (int T = 0; T < 8; T++) {
        if (T < 7) prefetch_chunk(xb4, T + 1, stg_s + ((T + 1) & 1) * 4096, lane, s0, s1);
        else       prefetch_chunk(xp4, 0,     stg_s, lane, s0, s1);   // ((7+1)&1)=0
        CPWAIT(1);
        __syncwarp();
        compute_chunk(stage + (T & 1) * 1024, T, T1B, WOB, lane, aO0, aO1, acc0, acc1);
    }
#pragma unroll
    for (int q = 0; q < 8; q++) {
        l1a[q] = lo32(acc0[q]) + hi32(acc0[q]) + M1B[q] * mob0 + B1B[q];
        l1b[q] = lo32(acc1[q]) + hi32(acc1[q]) + M1B[q] * mob1 + B1B[q];
        acc0[q] = 0; acc1[q] = 0;
    }

    // ---- pass 2 (x_pa)
#pragma unroll 2
    for (int T = 0; T < 8; T++) {
        if (T < 7) {
            prefetch_chunk(xp4, T + 1, stg_s + ((T + 1) & 1) * 4096, lane, s0, s1);
            CPWAIT(1);
        } else {
            CPWAIT(0);
        }
        __syncwarp();
        compute_chunk(stage + (T & 1) * 1024, T, T1P, WOP, lane, aO0, aO1, acc0, acc1);
    }
#pragma unroll
    for (int q = 0; q < 8; q++) {
        l1a[8 + q] = lo32(acc0[q]) + hi32(acc0[q]) + M1P[q] * mob0 + B1P[q];
        l1b[8 + q] = lo32(acc1[q]) + hi32(acc1[q]) + M1P[q] * mob1 + B1P[q];
    }

    // activations -> packed pairs [sq(16), l1(16)] clipped to [0,1]
    const float F = 255.0f / 256.0f;
    u64 c2a[16], c2b[16];
#pragma unroll
    for (int k = 0; k < 8; k++) {
        c2a[k] = pk(fminf(l1a[2 * k] * l1a[2 * k] * F, 1.0f),
                    fminf(l1a[2 * k + 1] * l1a[2 * k + 1] * F, 1.0f));
        c2a[8 + k] = pk(fminf(fmaxf(l1a[2 * k], 0.0f), 1.0f),
                        fminf(fmaxf(l1a[2 * k + 1], 0.0f), 1.0f));
        c2b[k] = pk(fminf(l1b[2 * k] * l1b[2 * k] * F, 1.0f),
                    fminf(l1b[2 * k + 1] * l1b[2 * k + 1] * F, 1.0f));
        c2b[8 + k] = pk(fminf(fmaxf(l1b[2 * k], 0.0f), 1.0f),
                        fminf(fmaxf(l1b[2 * k + 1], 0.0f), 1.0f));
    }

    // layer2 fused with Wout[0:64]; W2 loads shared across both groups
    float osum0 = 0.0f, osum1 = 0.0f;
#pragma unroll 2
    for (int o = 0; o < 64; o++) {
        const ulonglong2* wrow = W2T + o * 8;
        u64 ta0 = 0, tb0 = 0, ta1 = 0, tb1 = 0;
#pragma unroll
        for (int j = 0; j < 8; j++) {
            ulonglong2 w = wrow[j];
            ta0 = f2fma(w.x, c2a[2 * j], ta0);
            tb0 = f2fma(w.y, c2a[2 * j + 1], tb0);
            ta1 = f2fma(w.x, c2b[2 * j], ta1);
            tb1 = f2fma(w.y, c2b[2 * j + 1], tb1);
        }
        float wo = WO2[o], bb = B2[o];
        float sv0 = lo32(ta0) + hi32(ta0) + lo32(tb0) + hi32(tb0) + bb;
        float av0 = fminf(fmaxf(sv0, 0.0f), 1.0f);
        osum0 = fmaf(wo, av0 * av0 * F, osum0);
        float sv1 = lo32(ta1) + hi32(ta1) + lo32(tb1) + hi32(tb1) + bb;
        float av1 = fminf(fmaxf(sv1, 0.0f), 1.0f);
        osum1 = fmaf(wo, av1 * av1 * F, osum1);
    }

    float bo = sw[SB_BOUT];
    if (a0) out[s0] = lo32(aO0) + hi32(aO0) + osum0 + bo;
    if (a1) out[s1] = lo32(aO1) + hi32(aO1) + osum1 + bo;
}

// ---------------- launch ----------------
extern "C" void kernel_launch(void* const* d_in, const int* in_sizes, int n_in,
                              void* d_out, int out_size) {
    const float4* xb = (const float4*)d_in[0];
    const float4* xp = (const float4*)d_in[1];
    const float* mob = (const float*)d_in[2];
    const int* ply = (const int*)d_in[3];
    const float* W1b = (const float*)d_in[4];
    const float* b1b = (const float*)d_in[5];
    const float* W1pa = (const float*)d_in[6];
    const float* b1pa = (const float*)d_in[7];
    const float* W2 = (const float*)d_in[8];
    const float* b2 = (const float*)d_in[9];
    const float* Wout = (const float*)d_in[10];
    const float* bout = (const float*)d_in[11];
    float* out = (float*)d_out;
    int n = in_sizes[3];

    int nmb = (n + SPB - 1) / SPB + NB;
    if (nmb > MAX_BLK) nmb = MAX_BLK;

    cudaFuncSetAttribute(k_main, cudaFuncAttributeMaxDynamicSharedMemorySize, SMEM_BYTES);

    kA<<<(n + 255) / 256, 256>>>(W1b, b1b, W1pa, b1pa, W2, b2, Wout, bout, ply, n);
    kB<<<(nmb * SPB + 255) / 256, 256>>>(ply, n, nmb);
    k_main<<<nmb, MAIN_THREADS, SMEM_BYTES>>>(xb, xp, mob, out);
}

// round 8
// speedup vs baseline: 1.8567x; 1.2041x over previous
#include <cuda_runtime.h>
#include <cstdint>

typedef unsigned long long u64;

#define NB 6
#define BUCKET 10
#define MAX_BLK 520
#define MAX_HB 1040
#define PERM_CAP (MAX_BLK * 512)     // 266240
#define SPB 512                      // samples per main block
#define MAIN_THREADS 256

// ---- packed weight image (global) float offsets, per-bucket-contiguous ----
#define OFF_T1B 0                // [c][ip(64)][o(8)] pairs: 6*1024
#define OFF_T1P 6144
#define OFF_WOB 12288            // [c][ip(64)] pairs: 6*128
#define OFF_WOP 13056
#define OFF_W2  13824            // [c][o(64)][jj(16)] pairs: 6*2048
#define OFF_WO2 26112            // [c][64]
#define OFF_M1B 26496            // [c][8]
#define OFF_M1P 26544
#define OFF_B1B 26592
#define OFF_B1P 26640
#define OFF_B2  26688            // [c][64]
#define OFF_BOUT 27072           // [c]
#define WPK_F   27080

// ---- per-bucket smem weight layout (floats) ----
#define SB_T1B 0
#define SB_T1P 1024
#define SB_WOB 2048
#define SB_WOP 2176
#define SB_W2  2304
#define SB_WO2 4352
#define SB_M1B 4416
#define SB_M1P 4424
#define SB_B1B 4432
#define SB_B1P 4440
#define SB_B2  4448
#define SB_BOUT 4512
#define SB_END 4520              // 16B aligned (18080 bytes)

#define STAGE_F_PER_WARP 2048    // 2 buffers x 4KB
#define SMEM_FLOATS (SB_END + 8 * STAGE_F_PER_WARP)   // 20904
#define SMEM_BYTES  (SMEM_FLOATS * 4)                 // 83616

__device__ int   g_perm[PERM_CAP];
__device__ int   g_bh[MAX_HB][NB];     // per-256-block histograms
__device__ int   g_bs[MAX_HB][NB];     // per-block exclusive prefix within bucket
__device__ int   g_startp[NB + 1];     // padded bucket starts; [NB] = total
__device__ int   g_cntb[NB];           // bucket totals
__device__ int   g_blkc[MAX_BLK];
__device__ float g_wpk[WPK_F];

// ---------------- helpers ----------------
__device__ __forceinline__ u64 f2fma(u64 a, u64 b, u64 c) {
    u64 d;
    asm("fma.rn.f32x2 %0, %1, %2, %3;" : "=l"(d) : "l"(a), "l"(b), "l"(c));
    return d;
}
__device__ __forceinline__ float lo32(u64 a) { return __uint_as_float((unsigned)a); }
__device__ __forceinline__ float hi32(u64 a) { return __uint_as_float((unsigned)(a >> 32)); }
__device__ __forceinline__ u64 pk(float lo, float hi) {
    u64 r;
    asm("mov.b64 %0, {%1, %2};" : "=l"(r) : "f"(lo), "f"(hi));
    return r;
}
#define CP16(saddr, gptr) \
    asm volatile("cp.async.cg.shared.global [%0], [%1], 16;" :: "r"(saddr), "l"(gptr))
#define CPCOMMIT() asm volatile("cp.async.commit_group;")
#define CPWAIT(n)  asm volatile("cp.async.wait_group %0;" :: "n"(n))

// ---------------- kA: pack weights + per-block histogram (no global atomics) ----
__global__ void kA(const float* __restrict__ W1b, const float* __restrict__ b1b,
                   const float* __restrict__ W1pa, const float* __restrict__ b1pa,
                   const float* __restrict__ W2, const float* __restrict__ b2,
                   const float* __restrict__ Wout, const float* __restrict__ bout,
                   const int* __restrict__ ply, int n) {
    __shared__ int h[NB];
    int tid = threadIdx.x;
    if (tid < NB) h[tid] = 0;
    __syncthreads();
    int i = blockIdx.x * blockDim.x + tid;

    if (i < WPK_F) {
        float v = 0.0f;
        if (i < OFF_T1P) {
            int hh = i & 1, t = i >> 1;
            int o = t & 7, ip = (t >> 3) & 63, c = t >> 9;
            v = W1b[(c * 8 + o) * 129 + 2 * ip + hh];
        } else if (i < OFF_WOB) {
            int j = i - OFF_T1P;
            int hh = j & 1, t = j >> 1;
            int o = t & 7, ip = (t >> 3) & 63, c = t >> 9;
            v = W1pa[(c * 8 + o) * 129 + 2 * ip + hh];
        } else if (i < OFF_WOP) {
            int j = i - OFF_WOB;
            int hh = j & 1, t = j >> 1;
            int ip = t & 63, c = t >> 6;
            v = Wout[c * 320 + 64 + 2 * ip + hh];
        } else if (i < OFF_W2) {
            int j = i - OFF_WOP;
            int hh = j & 1, t = j >> 1;
            int ip = t & 63, c = t >> 6;
            v = Wout[c * 320 + 192 + 2 * ip + hh];
        } else if (i < OFF_WO2) {
            int j = i - OFF_W2;
            int hh = j & 1, t = j >> 1;
            int jj = t & 15, o = (t >> 4) & 63, c = t >> 10;
            v = W2[(c * 64 + o) * 32 + 2 * jj + hh];
        } else if (i < OFF_M1B) {
            int j = i - OFF_WO2;
            int o = j & 63, c = j >> 6;
            v = Wout[c * 320 + o];
        } else if (i < OFF_M1P) {
            int j = i - OFF_M1B;
            int o = j & 7, c = j >> 3;
            v = W1b[(c * 8 + o) * 129 + 128];
        } else if (i < OFF_B1B) {
            int j = i - OFF_M1P;
            int o = j & 7, c = j >> 3;
            v = W1pa[(c * 8 + o) * 129 + 128];
        } else if (i < OFF_B1P) {
            v = b1b[i - OFF_B1B];
        } else if (i < OFF_B2) {
            v = b1pa[i - OFF_B1P];
        } else if (i < OFF_BOUT) {
            v = b2[i - OFF_B2];
        } else {
            v = bout[i - OFF_BOUT];
        }
        g_wpk[i] = v;
    }
    if (i < n) {
        int c = ply[i] / BUCKET;
        c = min(max(c, 0), NB - 1);
        atomicAdd(&h[c], 1);            // smem only
    }
    __syncthreads();
    if (tid < NB) g_bh[blockIdx.x][tid] = h[tid];
}

// ---------------- kS: single-block scan (per-bucket block prefixes + starts + blkc) ----
__global__ void kS(int nhb, int nmb) {
    __shared__ int tot[NB];
    int w = threadIdx.x >> 5;
    int lane = threadIdx.x & 31;
    if (w < NB) {
        int run = 0;
        for (int b0 = 0; b0 < nhb; b0 += 32) {
            int b = b0 + lane;
            int v = (b < nhb) ? g_bh[b][w] : 0;
            int x = v;
#pragma unroll
            for (int d = 1; d < 32; d <<= 1) {
                int y = __shfl_up_sync(0xffffffffu, x, d);
                if (lane >= d) x += y;
            }
            if (b < nhb) g_bs[b][w] = run + (x - v);
            run += __shfl_sync(0xffffffffu, x, 31);
        }
        if (lane == 0) tot[w] = run;
    }
    __syncthreads();
    if (threadIdx.x == 0) {
        int base = 0;
        for (int c = 0; c < NB; c++) {
            g_startp[c] = base;
            g_cntb[c] = tot[c];
            base += ((tot[c] + SPB - 1) / SPB) * SPB;
        }
        g_startp[NB] = base;
    }
    __syncthreads();
    int total = g_startp[NB];
    for (int j = threadIdx.x; j < nmb; j += blockDim.x) {
        int b = j * SPB;
        int bc = -1;
        if (b < total) {
#pragma unroll
            for (int cc = 0; cc < NB; cc++) {
                if (b >= g_startp[cc] && b < g_startp[cc + 1]) bc = cc;
            }
        }
        g_blkc[j] = bc;
    }
}

// ---------------- kC: scatter (smem ranks, no global atomics) + pad-fill ----
__global__ void kC(const int* __restrict__ ply, int n) {
    __shared__ int sh[NB];
    int tid = threadIdx.x;
    if (tid < NB) sh[tid] = 0;
    __syncthreads();
    int i = blockIdx.x * blockDim.x + tid;

    int c = -1, r = 0;
    if (i < n) {
        c = ply[i] / BUCKET;
        c = min(max(c, 0), NB - 1);
        r = atomicAdd(&sh[c], 1);       // smem only; order-free
    }
    if (c >= 0) {
        g_perm[g_startp[c] + g_bs[blockIdx.x][c] + r] = i;
    }

    int total = g_startp[NB];
    if (i < total) {
#pragma unroll
        for (int cc = 0; cc < NB; cc++) {
            if (i >= g_startp[cc] + g_cntb[cc] && i < g_startp[cc + 1])
                g_perm[i] = -1;
        }
    }
}

// ---------------- main kernel (unchanged from 122.9us version) ----------------
__device__ __forceinline__ void prefetch_chunk(
    const float4* __restrict__ src, int T, uint32_t sbuf,
    int lane, int s0, int s1) {
    const int rl = lane & 7;
    const int col = lane >> 3;
#pragma unroll
    for (int k = 0; k < 4; k++) {
        int row = k * 8 + rl;
        int r0 = __shfl_sync(0xffffffffu, s0, row);
        const float4* gp0 = src + (size_t)r0 * 32 + T * 4 + col;
        CP16(sbuf + row * 128 + ((col ^ rl) << 4), gp0);
        int r1 = __shfl_sync(0xffffffffu, s1, row);
        const float4* gp1 = src + (size_t)r1 * 32 + T * 4 + col;
        CP16(sbuf + row * 128 + (((4 + col) ^ rl) << 4), gp1);
    }
    CPCOMMIT();
}

__device__ __forceinline__ void compute_chunk(
    const float* __restrict__ buf, int T,
    const ulonglong2* __restrict__ T1, const u64* __restrict__ WO,
    int lane, u64& aO0, u64& aO1, u64 acc0[8], u64 acc1[8]) {
    const char* bc = (const char*)buf + lane * 128;
    const int rl = lane & 7;
#pragma unroll
    for (int j = 0; j < 4; j++) {
        ulonglong2 xv0 = *(const ulonglong2*)(bc + ((j ^ rl) << 4));
        ulonglong2 xv1 = *(const ulonglong2*)(bc + (((4 + j) ^ rl) << 4));
        int ip0 = T * 8 + 2 * j;
        int ip1 = ip0 + 1;
        ulonglong2 wA0 = T1[ip0 * 4 + 0], wB0 = T1[ip0 * 4 + 1];
        ulonglong2 wC0 = T1[ip0 * 4 + 2], wD0 = T1[ip0 * 4 + 3];
        ulonglong2 wA1 = T1[ip1 * 4 + 0], wB1 = T1[ip1 * 4 + 1];
        ulonglong2 wC1 = T1[ip1 * 4 + 2], wD1 = T1[ip1 * 4 + 3];
        u64 wo0 = WO[ip0], wo1 = WO[ip1];
        acc0[0] = f2fma(wA0.x, xv0.x, acc0[0]);
        acc0[1] = f2fma(wA0.y, xv0.x, acc0[1]);
        acc0[2] = f2fma(wB0.x, xv0.x, acc0[2]);
        acc0[3] = f2fma(wB0.y, xv0.x, acc0[3]);
        acc0[4] = f2fma(wC0.x, xv0.x, acc0[4]);
        acc0[5] = f2fma(wC0.y, xv0.x, acc0[5]);
        acc0[6] = f2fma(wD0.x, xv0.x, acc0[6]);
        acc0[7] = f2fma(wD0.y, xv0.x, acc0[7]);
        aO0 = f2fma(wo0, xv0.x, aO0);
        acc0[0] = f2fma(wA1.x, xv0.y, acc0[0]);
        acc0[1] = f2fma(wA1.y, xv0.y, acc0[1]);
        acc0[2] = f2fma(wB1.x, xv0.y, acc0[2]);
        acc0[3] = f2fma(wB1.y, xv0.y, acc0[3]);
        acc0[4] = f2fma(wC1.x, xv0.y, acc0[4]);
        acc0[5] = f2fma(wC1.y, xv0.y, acc0[5]);
        acc0[6] = f2fma(wD1.x, xv0.y, acc0[6]);
        acc0[7] = f2fma(wD1.y, xv0.y, acc0[7]);
        aO0 = f2fma(wo1, xv0.y, aO0);
        acc1[0] = f2fma(wA0.x, xv1.x, acc1[0]);
        acc1[1] = f2fma(wA0.y, xv1.x, acc1[1]);
        acc1[2] = f2fma(wB0.x, xv1.x, acc1[2]);
        acc1[3] = f2fma(wB0.y, xv1.x, acc1[3]);
        acc1[4] = f2fma(wC0.x, xv1.x, acc1[4]);
        acc1[5] = f2fma(wC0.y, xv1.x, acc1[5]);
        acc1[6] = f2fma(wD0.x, xv1.x, acc1[6]);
        acc1[7] = f2fma(wD0.y, xv1.x, acc1[7]);
        aO1 = f2fma(wo0, xv1.x, aO1);
        acc1[0] = f2fma(wA1.x, xv1.y, acc1[0]);
        acc1[1] = f2fma(wA1.y, xv1.y, acc1[1]);
        acc1[2] = f2fma(wB1.x, xv1.y, acc1[2]);
        acc1[3] = f2fma(wB1.y, xv1.y, acc1[3]);
        acc1[4] = f2fma(wC1.x, xv1.y, acc1[4]);
        acc1[5] = f2fma(wC1.y, xv1.y, acc1[5]);
        acc1[6] = f2fma(wD1.x, xv1.y, acc1[6]);
        acc1[7] = f2fma(wD1.y, xv1.y, acc1[7]);
        aO1 = f2fma(wo1, xv1.y, aO1);
    }
}

__global__ __launch_bounds__(MAIN_THREADS, 2)
void k_main(const float4* __restrict__ xb4, const float4* __restrict__ xp4,
            const float* __restrict__ mobv, float* __restrict__ out) {
    int c = g_blkc[blockIdx.x];
    if (c < 0) return;

    extern __shared__ float sw[];
    const int lane = threadIdx.x & 31;
    const int wid = threadIdx.x >> 5;
    float* stage = sw + SB_END + wid * STAGE_F_PER_WARP;
    uint32_t stg_s = (uint32_t)__cvta_generic_to_shared(stage);

    int base = blockIdx.x * SPB + wid * 64 + lane;
    int e0 = g_perm[base];
    int e1 = g_perm[base + 32];
    bool a0 = e0 >= 0, a1 = e1 >= 0;
    int s0 = a0 ? e0 : 0;
    int s1 = a1 ? e1 : 0;
    float mv0 = __ldg(mobv + s0);
    float mv1 = __ldg(mobv + s1);
    prefetch_chunk(xb4, 0, stg_s, lane, s0, s1);

    {
        const int tid = threadIdx.x;
        const float4* w1 = (const float4*)(g_wpk + OFF_T1B + c * 1024);
        const float4* w2 = (const float4*)(g_wpk + OFF_T1P + c * 1024);
        float4* d1 = (float4*)(sw + SB_T1B);
        float4* d2 = (float4*)(sw + SB_T1P);
        for (int i = tid; i < 256; i += MAIN_THREADS) { d1[i] = w1[i]; d2[i] = w2[i]; }
        const float4* w5 = (const float4*)(g_wpk + OFF_W2 + c * 2048);
        float4* d5 = (float4*)(sw + SB_W2);
        for (int i = tid; i < 512; i += MAIN_THREADS) d5[i] = w5[i];
        if (tid < 32) {
            ((float4*)(sw + SB_WOB))[tid] = ((const float4*)(g_wpk + OFF_WOB + c * 128))[tid];
            ((float4*)(sw + SB_WOP))[tid] = ((const float4*)(g_wpk + OFF_WOP + c * 128))[tid];
        } else if (tid < 64) {
            int j = tid - 32;
            if (j < 16) ((float4*)(sw + SB_WO2))[j] = ((const float4*)(g_wpk + OFF_WO2 + c * 64))[j];
        } else if (tid < 96) {
            int j = tid - 64;
            if (j < 16) ((float4*)(sw + SB_B2))[j] = ((const float4*)(g_wpk + OFF_B2 + c * 64))[j];
        } else if (tid < 128) {
            int j = tid - 96;
            if (j < 8) {
                sw[SB_M1B + j] = g_wpk[OFF_M1B + c * 8 + j];
                sw[SB_M1P + j] = g_wpk[OFF_M1P + c * 8 + j];
                sw[SB_B1B + j] = g_wpk[OFF_B1B + c * 8 + j];
                sw[SB_B1P + j] = g_wpk[OFF_B1P + c * 8 + j];
            }
            if (j == 0) sw[SB_BOUT] = g_wpk[OFF_BOUT + c];
        }
    }
    __syncthreads();

    const ulonglong2* T1B = (const ulonglong2*)(sw + SB_T1B);
    const ulonglong2* T1P = (const ulonglong2*)(sw + SB_T1P);
    const u64* WOB = (const u64*)(sw + SB_WOB);
    const u64* WOP = (const u64*)(sw + SB_WOP);
    const ulonglong2* W2T = (const ulonglong2*)(sw + SB_W2);
    const float* WO2 = sw + SB_WO2;
    const float* M1B = sw + SB_M1B;
    const float* M1P = sw + SB_M1P;
    const float* B1B = sw + SB_B1B;
    const float* B1P = sw + SB_B1P;
    const float* B2 = sw + SB_B2;

    float mob0 = fminf(mv0 * (7.0f / 255.0f), 1.0f);
    float mob1 = fminf(mv1 * (7.0f / 255.0f), 1.0f);

    u64 aO0 = 0, aO1 = 0;
    u64 acc0[8], acc1[8];
    float l1a[16], l1b[16];

#pragma unroll
    for (int q = 0; q < 8; q++) { acc0[q] = 0; acc1[q] = 0; }

#pragma unroll 2
    for (int T = 0; T < 8; T++) {
        if (T < 7) prefetch_chunk(xb4, T + 1, stg_s + ((T + 1) & 1) * 4096, lane, s0, s1);
        else       prefetch_chunk(xp4, 0,     stg_s, lane, s0, s1);
        CPWAIT(1);
        __syncwarp();
        compute_chunk(stage + (T & 1) * 1024, T, T1B, WOB, lane, aO0, aO1, acc0, acc1);
    }
#pragma unroll
    for (int q = 0; q < 8; q++) {
        l1a[q] = lo32(acc0[q]) + hi32(acc0[q]) + M1B[q] * mob0 + B1B[q];
        l1b[q] = lo32(acc1[q]) + hi32(acc1[q]) + M1B[q] * mob1 + B1B[q];
        acc0[q] = 0; acc1[q] = 0;
    }

#pragma unroll 2
    for (int T = 0; T < 8; T++) {
        if (T < 7) {
            prefetch_chunk(xp4, T + 1, stg_s + ((T + 1) & 1) * 4096, lane, s0, s1);
            CPWAIT(1);
        } else {
            CPWAIT(0);
        }
        __syncwarp();
        compute_chunk(stage + (T & 1) * 1024, T, T1P, WOP, lane, aO0, aO1, acc0, acc1);
    }
#pragma unroll
    for (int q = 0; q < 8; q++) {
        l1a[8 + q] = lo32(acc0[q]) + hi32(acc0[q]) + M1P[q] * mob0 + B1P[q];
        l1b[8 + q] = lo32(acc1[q]) + hi32(acc1[q]) + M1P[q] * mob1 + B1P[q];
    }

    const float F = 255.0f / 256.0f;
    u64 c2a[16], c2b[16];
#pragma unroll
    for (int k = 0; k < 8; k++) {
        c2a[k] = pk(fminf(l1a[2 * k] * l1a[2 * k] * F, 1.0f),
                    fminf(l1a[2 * k + 1] * l1a[2 * k + 1] * F, 1.0f));
        c2a[8 + k] = pk(fminf(fmaxf(l1a[2 * k], 0.0f), 1.0f),
                        fminf(fmaxf(l1a[2 * k + 1], 0.0f), 1.0f));
        c2b[k] = pk(fminf(l1b[2 * k] * l1b[2 * k] * F, 1.0f),
                    fminf(l1b[2 * k + 1] * l1b[2 * k + 1] * F, 1.0f));
        c2b[8 + k] = pk(fminf(fmaxf(l1b[2 * k], 0.0f), 1.0f),
                        fminf(fmaxf(l1b[2 * k + 1], 0.0f), 1.0f));
    }

    float osum0 = 0.0f, osum1 = 0.0f;
#pragma unroll 2
    for (int o = 0; o < 64; o++) {
        const ulonglong2* wrow = W2T + o * 8;
        u64 ta0 = 0, tb0 = 0, ta1 = 0, tb1 = 0;
#pragma unroll
        for (int j = 0; j < 8; j++) {
            ulonglong2 w = wrow[j];
            ta0 = f2fma(w.x, c2a[2 * j], ta0);
            tb0 = f2fma(w.y, c2a[2 * j + 1], tb0);
            ta1 = f2fma(w.x, c2b[2 * j], ta1);
            tb1 = f2fma(w.y, c2b[2 * j + 1], tb1);
        }
        float wo = WO2[o], bb = B2[o];
        float sv0 = lo32(ta0) + hi32(ta0) + lo32(tb0) + hi32(tb0) + bb;
        float av0 = fminf(fmaxf(sv0, 0.0f), 1.0f);
        osum0 = fmaf(wo, av0 * av0 * F, osum0);
        float sv1 = lo32(ta1) + hi32(ta1) + lo32(tb1) + hi32(tb1) + bb;
        float av1 = fminf(fmaxf(sv1, 0.0f), 1.0f);
        osum1 = fmaf(wo, av1 * av1 * F, osum1);
    }

    float bo = sw[SB_BOUT];
    if (a0) out[s0] = lo32(aO0) + hi32(aO0) + osum0 + bo;
    if (a1) out[s1] = lo32(aO1) + hi32(aO1) + osum1 + bo;
}

// ---------------- launch ----------------
extern "C" void kernel_launch(void* const* d_in, const int* in_sizes, int n_in,
                              void* d_out, int out_size) {
    const float4* xb = (const float4*)d_in[0];
    const float4* xp = (const float4*)d_in[1];
    const float* mob = (const float*)d_in[2];
    const int* ply = (const int*)d_in[3];
    const float* W1b = (const float*)d_in[4];
    const float* b1b = (const float*)d_in[5];
    const float* W1pa = (const float*)d_in[6];
    const float* b1pa = (const float*)d_in[7];
    const float* W2 = (const float*)d_in[8];
    const float* b2 = (const float*)d_in[9];
    const float* Wout = (const float*)d_in[10];
    const float* bout = (const float*)d_in[11];
    float* out = (float*)d_out;
    int n = in_sizes[3];

    int nhb = (n + 255) / 256;
    if (nhb > MAX_HB) nhb = MAX_HB;
    int nmb = (n + SPB - 1) / SPB + NB;
    if (nmb > MAX_BLK) nmb = MAX_BLK;

    cudaFuncSetAttribute(k_main, cudaFuncAttributeMaxDynamicSharedMemorySize, SMEM_BYTES);

    kA<<<nhb, 256>>>(W1b, b1b, W1pa, b1pa, W2, b2, Wout, bout, ply, n);
    kS<<<1, 256>>>(nhb, nmb);
    kC<<<(nmb * SPB + 255) / 256, 256>>>(ply, n);
    k_main<<<nmb, MAIN_THREADS, SMEM_BYTES>>>(xb, xp, mob, out);
}